// round 7
// baseline (speedup 1.0000x reference)
#include <cuda_runtime.h>
#include <cstdint>

// Problem-fixed sizes (GraphNet_57432302682564): N=150000, E=4800000
// Strategy: the 3-layer SAGE stack has no nonlinearity between layers, so the
// whole network is affine in h0. We only need A*h0, A^2*h0 (full graph, 8ch)
// and A^3*h0 / A^2*1 / A*1 restricted to the 68 output rows; the weight
// matrices collapse into four [8,3] combine matrices computed once in k_final.
#define NN    150000
#define NPAD  150016
#define EE    4800000
#define NOUT  68

// ---------------- scratch (device globals; no allocation allowed) ----------------
__device__ float4 g_P0[NPAD * 2];   // h0 = [x | tanh(pos)]  [N,8]
__device__ float4 g_S1[NPAD * 2];   // sum P0[src] -> normalized in place to A*P0
__device__ float4 g_S2[NPAD * 2];   // sum_{j->i} (A P0)[j]  [N,8]
__device__ int    g_cnt[NPAD];      // in-degree
__device__ float  g_S3[NOUT * 12];  // per out row: 8ch sum of P2[src]; ch8: sum u[src]
__device__ unsigned int g_list[EE]; // packed edges with dst < NOUT: (dst<<25)|src
__device__ int    g_nlist;

// ---------------- helpers ----------------
__device__ __forceinline__ void red_v4(float* addr, float a, float b, float c, float d) {
    asm volatile("red.global.add.v4.f32 [%0], {%1,%2,%3,%4};"
                 :: "l"(addr), "f"(a), "f"(b), "f"(c), "f"(d)
                 : "memory");
}
__device__ __forceinline__ void red_s32(int* addr, int v) {
    asm volatile("red.global.add.s32 [%0], %1;" :: "l"(addr), "r"(v) : "memory");
}

// ---------------- K0: build P0, zero accumulators ----------------
__global__ void k_init(const float* __restrict__ x,
                       const float* __restrict__ wpos,
                       const float* __restrict__ bpos,
                       int n)
{
    int i = blockIdx.x * blockDim.x + threadIdx.x;
    if (i < n) {
        float fi = (float)i;
        float4 a, b;
        a.x = x[i * 3 + 0];
        a.y = x[i * 3 + 1];
        a.z = x[i * 3 + 2];
        a.w = tanhf(fi * wpos[0] + bpos[0]);
        b.x = tanhf(fi * wpos[1] + bpos[1]);
        b.y = tanhf(fi * wpos[2] + bpos[2]);
        b.z = tanhf(fi * wpos[3] + bpos[3]);
        b.w = tanhf(fi * wpos[4] + bpos[4]);
        g_P0[i * 2]     = a;
        g_P0[i * 2 + 1] = b;
        float4 z = make_float4(0.f, 0.f, 0.f, 0.f);
        g_S1[i * 2] = z; g_S1[i * 2 + 1] = z;
        g_S2[i * 2] = z; g_S2[i * 2 + 1] = z;
        g_cnt[i] = 0;
    }
    if (i < NOUT * 12) g_S3[i] = 0.f;
    if (i == 0) g_nlist = 0;
}

// ---------------- K1: edge pass 1 (aggregate P0, count degrees, collect small edges) ----------------
__global__ void k_edge1(const int* __restrict__ srcs, const int* __restrict__ dsts, int e)
{
    int t = blockIdx.x * blockDim.x + threadIdx.x;
    int base = t * 4;
    bool vecok = ((e & 3) == 0);
    if (vecok && base + 3 < e) {
        int4 s4 = *(const int4*)(srcs + base);
        int4 d4 = *(const int4*)(dsts + base);
        int s[4] = {s4.x, s4.y, s4.z, s4.w};
        int d[4] = {d4.x, d4.y, d4.z, d4.w};
        #pragma unroll
        for (int k = 0; k < 4; k++) {
            float4 a = g_P0[s[k] * 2];
            float4 b = g_P0[s[k] * 2 + 1];
            float* dp = (float*)&g_S1[d[k] * 2];
            red_v4(dp,     a.x, a.y, a.z, a.w);
            red_v4(dp + 4, b.x, b.y, b.z, b.w);
            red_s32(&g_cnt[d[k]], 1);
            if (d[k] < NOUT) {
                int idx = atomicAdd(&g_nlist, 1);
                if (idx < EE)
                    g_list[idx] = ((unsigned)d[k] << 25) | (unsigned)s[k];
            }
        }
    } else {
        for (int k = base; k < e && k < base + 4; k++) {
            int s = srcs[k], d = dsts[k];
            float4 a = g_P0[s * 2];
            float4 b = g_P0[s * 2 + 1];
            float* dp = (float*)&g_S1[d * 2];
            red_v4(dp,     a.x, a.y, a.z, a.w);
            red_v4(dp + 4, b.x, b.y, b.z, b.w);
            red_s32(&g_cnt[d], 1);
            if (d < NOUT) {
                int idx = atomicAdd(&g_nlist, 1);
                if (idx < EE)
                    g_list[idx] = ((unsigned)d << 25) | (unsigned)s;
            }
        }
    }
}

// ---------------- K2: normalize S1 in place -> P1 = A P0 ----------------
__global__ void k_norm1(int n)
{
    int i = blockIdx.x * blockDim.x + threadIdx.x;
    if (i >= n) return;
    int c = g_cnt[i];
    float inv = 1.f / (float)(c > 1 ? c : 1);
    float4 a = g_S1[i * 2], b = g_S1[i * 2 + 1];
    a.x *= inv; a.y *= inv; a.z *= inv; a.w *= inv;
    b.x *= inv; b.y *= inv; b.z *= inv; b.w *= inv;
    g_S1[i * 2]     = a;   // in place: same L2 lines, no second buffer
    g_S1[i * 2 + 1] = b;
}

// ---------------- K3: edge pass 2 (aggregate P1 = normalized S1) ----------------
__global__ void k_edge2(const int* __restrict__ srcs, const int* __restrict__ dsts, int e)
{
    int t = blockIdx.x * blockDim.x + threadIdx.x;
    int base = t * 4;
    bool vecok = ((e & 3) == 0);
    if (vecok && base + 3 < e) {
        int4 s4 = *(const int4*)(srcs + base);
        int4 d4 = *(const int4*)(dsts + base);
        int s[4] = {s4.x, s4.y, s4.z, s4.w};
        int d[4] = {d4.x, d4.y, d4.z, d4.w};
        #pragma unroll
        for (int k = 0; k < 4; k++) {
            float4 a = g_S1[s[k] * 2];
            float4 b = g_S1[s[k] * 2 + 1];
            float* dp = (float*)&g_S2[d[k] * 2];
            red_v4(dp,     a.x, a.y, a.z, a.w);
            red_v4(dp + 4, b.x, b.y, b.z, b.w);
        }
    } else {
        for (int k = base; k < e && k < base + 4; k++) {
            int s = srcs[k], d = dsts[k];
            float4 a = g_S1[s * 2];
            float4 b = g_S1[s * 2 + 1];
            float* dp = (float*)&g_S2[d * 2];
            red_v4(dp,     a.x, a.y, a.z, a.w);
            red_v4(dp + 4, b.x, b.y, b.z, b.w);
        }
    }
}

// ---------------- K4: small edge pass (dst < NOUT): aggregate P2 = S2/cnt and u-sums ----------------
__global__ void k_small()
{
    int nl = g_nlist;
    if (nl > EE) nl = EE;
    for (int t = blockIdx.x * blockDim.x + threadIdx.x; t < nl;
         t += gridDim.x * blockDim.x) {
        unsigned p = g_list[t];
        int s = (int)(p & 0x1FFFFFFu);
        int d = (int)(p >> 25);
        int c = g_cnt[s];
        float inv = 1.f / (float)(c > 1 ? c : 1);
        float u = (c > 0) ? 1.f : 0.f;
        float4 a = g_S2[s * 2], b = g_S2[s * 2 + 1];
        float* dp = &g_S3[d * 12];
        red_v4(dp,     a.x * inv, a.y * inv, a.z * inv, a.w * inv);
        red_v4(dp + 4, b.x * inv, b.y * inv, b.z * inv, b.w * inv);
        atomicAdd(dp + 8, u);
    }
}

// ---------------- K5: combine matrices + final 68x3 output ----------------
__global__ void k_final(const float* __restrict__ Wl1, const float* __restrict__ Wr1,
                        const float* __restrict__ b1,
                        const float* __restrict__ Wl2, const float* __restrict__ Wr2,
                        const float* __restrict__ b2,
                        const float* __restrict__ Wl3, const float* __restrict__ Wr3,
                        const float* __restrict__ b3,
                        float* __restrict__ out)
{
    __shared__ float sLL[8][16], sMix[8][16], sRR[8][16];
    __shared__ float sC3[8][3], sC2[8][3], sC1[8][3], sC0[8][3];
    __shared__ float sbL2[16], sbR2[16], scv[3], scu[3], scc[3];
    int t = threadIdx.x;

    // Stage 1: 2-layer products [8,16]
    if (t < 128) {
        int i = t >> 4, j = t & 15;
        float ll = 0.f, mx = 0.f, rr = 0.f;
        #pragma unroll
        for (int k = 0; k < 16; k++) {
            float l1 = Wl1[i * 16 + k], r1 = Wr1[i * 16 + k];
            float l2 = Wl2[k * 16 + j], r2 = Wr2[k * 16 + j];
            ll += l1 * l2;
            mx += r1 * l2 + l1 * r2;
            rr += r1 * r2;
        }
        sLL[i][j] = ll; sMix[i][j] = mx; sRR[i][j] = rr;
    }
    if (t < 16) {
        float bl = 0.f, br = 0.f;
        #pragma unroll
        for (int k = 0; k < 16; k++) {
            bl += b1[k] * Wl2[k * 16 + t];
            br += b1[k] * Wr2[k * 16 + t];
        }
        sbL2[t] = bl;
        sbR2[t] = br + b2[t];
    }
    __syncthreads();

    // Stage 2: fold in layer 3 -> [8,3] combine matrices
    if (t < 24) {
        int i = t / 3, cc3 = t % 3;
        float c3 = 0.f, c2 = 0.f, c1 = 0.f, c0 = 0.f;
        #pragma unroll
        for (int k = 0; k < 16; k++) {
            float l3 = Wl3[k * 3 + cc3], r3 = Wr3[k * 3 + cc3];
            c3 += sLL[i][k] * l3;
            c2 += sMix[i][k] * l3 + sLL[i][k] * r3;
            c1 += sRR[i][k] * l3 + sMix[i][k] * r3;
            c0 += sRR[i][k] * r3;
        }
        sC3[i][cc3] = c3; sC2[i][cc3] = c2; sC1[i][cc3] = c1; sC0[i][cc3] = c0;
    }
    if (t < 3) {
        float cv = 0.f, cu = 0.f, cc = 0.f;
        #pragma unroll
        for (int k = 0; k < 16; k++) {
            float l3 = Wl3[k * 3 + t], r3 = Wr3[k * 3 + t];
            cv += sbL2[k] * l3;
            cu += sbR2[k] * l3 + sbL2[k] * r3;
            cc += sbR2[k] * r3;
        }
        scv[t] = cv; scu[t] = cu; scc[t] = cc + b3[t];
    }
    __syncthreads();

    // Stage 3: output rows
    if (t < NOUT) {
        int c = g_cnt[t];
        float inv = 1.f / (float)(c > 1 ? c : 1);
        float u = (c > 0) ? 1.f : 0.f;
        float P0r[8], P1r[8], P2r[8], P3r[8];
        float4 a, b;
        a = g_P0[t * 2]; b = g_P0[t * 2 + 1];
        P0r[0] = a.x; P0r[1] = a.y; P0r[2] = a.z; P0r[3] = a.w;
        P0r[4] = b.x; P0r[5] = b.y; P0r[6] = b.z; P0r[7] = b.w;
        a = g_S1[t * 2]; b = g_S1[t * 2 + 1];   // S1 now holds A*P0 (normalized in place)
        P1r[0] = a.x; P1r[1] = a.y; P1r[2] = a.z; P1r[3] = a.w;
        P1r[4] = b.x; P1r[5] = b.y; P1r[6] = b.z; P1r[7] = b.w;
        a = g_S2[t * 2]; b = g_S2[t * 2 + 1];
        P2r[0] = a.x * inv; P2r[1] = a.y * inv; P2r[2] = a.z * inv; P2r[3] = a.w * inv;
        P2r[4] = b.x * inv; P2r[5] = b.y * inv; P2r[6] = b.z * inv; P2r[7] = b.w * inv;
        #pragma unroll
        for (int k = 0; k < 8; k++) P3r[k] = g_S3[t * 12 + k] * inv;
        float v = g_S3[t * 12 + 8] * inv;

        #pragma unroll
        for (int cc3 = 0; cc3 < 3; cc3++) {
            float acc = scc[cc3] + u * scu[cc3] + v * scv[cc3];
            #pragma unroll
            for (int k = 0; k < 8; k++) {
                acc += P3r[k] * sC3[k][cc3]
                     + P2r[k] * sC2[k][cc3]
                     + P1r[k] * sC1[k][cc3]
                     + P0r[k] * sC0[k][cc3];
            }
            out[t * 3 + cc3] = acc;
        }
    }
}

// ---------------- launch ----------------
extern "C" void kernel_launch(void* const* d_in, const int* in_sizes, int n_in,
                              void* d_out, int out_size)
{
    const float* x    = (const float*)d_in[0];
    const int*   ei   = (const int*)  d_in[1];
    const float* wpos = (const float*)d_in[2];
    const float* bpos = (const float*)d_in[3];
    const float* Wl1  = (const float*)d_in[4];
    const float* Wr1  = (const float*)d_in[5];
    const float* b1   = (const float*)d_in[6];
    const float* Wl2  = (const float*)d_in[7];
    const float* Wr2  = (const float*)d_in[8];
    const float* b2   = (const float*)d_in[9];
    const float* Wl3  = (const float*)d_in[10];
    const float* Wr3  = (const float*)d_in[11];
    const float* b3   = (const float*)d_in[12];

    int n = in_sizes[0] / 3;
    int e = in_sizes[1] / 2;
    if (n > NPAD) n = NPAD;   // scratch capacity guard (problem-fixed N=150000)
    if (e > EE)   e = EE;

    int nb = (n + 255) / 256;
    if (nb < 4) nb = 4;       // ensure S3/counter zeroing coverage
    int eb = ((e + 3) / 4 + 255) / 256;

    k_init  <<<nb, 256>>>(x, wpos, bpos, n);
    k_edge1 <<<eb, 256>>>(ei, ei + e, e);
    k_norm1 <<<nb, 256>>>(n);
    k_edge2 <<<eb, 256>>>(ei, ei + e, e);
    k_small <<<64, 256>>>();
    k_final <<<1, 128>>>(Wl1, Wr1, b1, Wl2, Wr2, b2, Wl3, Wr3, b3, (float*)d_out);
}

// round 11
// speedup vs baseline: 1.9913x; 1.9913x over previous
#include <cuda_runtime.h>
#include <cstdint>

// Problem-fixed sizes (GraphNet_57432302682564): N=150000, E=4800000
// The 3-layer SAGE stack is affine in h0, so the output needs only:
//   A*h0   at bm1 rows (sources of edges into bm2, ~38% edge coverage)
//   A^2*h0 at bm2 rows (sources of edges into rows<68, ~1.5% edge coverage)
//   A^3*h0, A^2*1, A*1 at the 68 output rows
// with the weights collapsed into four [8,3] combine matrices (k_final).
#define NN    150000
#define NPAD  150016
#define EE    4800000
#define NOUT  68
#define BMW   (NPAD / 32)   // bitmap words = 4688

// ---------------- scratch (device globals; no allocation allowed) ----------------
__device__ float4 g_P0[NPAD * 2];   // h0 = [x | tanh(pos)]  [N,8]
__device__ float4 g_S1[NPAD * 2];   // sum P0[src] at bm1 rows -> normalized in place
__device__ float4 g_S2[NPAD * 2];   // sum S1[src] at bm2 rows
__device__ int    g_cnt[NPAD];      // in-degree (counted at bm1 rows only)
__device__ float  g_S3[NOUT * 12];  // per out row: 8ch sum of P2[src]; ch8: sum u[src]
__device__ unsigned int g_list[EE]; // packed edges with dst < NOUT: (dst<<25)|src
__device__ int    g_nlist;
__device__ unsigned int g_bm1[BMW]; // rows where S1/cnt are needed
__device__ unsigned int g_bm2[BMW]; // rows where S2 is needed

// ---------------- helpers ----------------
__device__ __forceinline__ void red_v4(float* addr, float a, float b, float c, float d) {
    asm volatile("red.global.add.v4.f32 [%0], {%1,%2,%3,%4};"
                 :: "l"(addr), "f"(a), "f"(b), "f"(c), "f"(d)
                 : "memory");
}
__device__ __forceinline__ void red_s32(int* addr, int v) {
    asm volatile("red.global.add.s32 [%0], %1;" :: "l"(addr), "r"(v) : "memory");
}
__device__ __forceinline__ bool bit_test(const unsigned int* bm, int i) {
    return (bm[i >> 5] >> (i & 31)) & 1u;
}

// ---------------- K0: build P0, zero accumulators + bitmaps ----------------
__global__ void k_init(const float* __restrict__ x,
                       const float* __restrict__ wpos,
                       const float* __restrict__ bpos,
                       int n)
{
    int i = blockIdx.x * blockDim.x + threadIdx.x;
    if (i < n) {
        float fi = (float)i;
        float4 a, b;
        a.x = x[i * 3 + 0];
        a.y = x[i * 3 + 1];
        a.z = x[i * 3 + 2];
        a.w = tanhf(fi * wpos[0] + bpos[0]);
        b.x = tanhf(fi * wpos[1] + bpos[1]);
        b.y = tanhf(fi * wpos[2] + bpos[2]);
        b.z = tanhf(fi * wpos[3] + bpos[3]);
        b.w = tanhf(fi * wpos[4] + bpos[4]);
        g_P0[i * 2]     = a;
        g_P0[i * 2 + 1] = b;
        float4 z = make_float4(0.f, 0.f, 0.f, 0.f);
        g_S1[i * 2] = z; g_S1[i * 2 + 1] = z;
        g_S2[i * 2] = z; g_S2[i * 2 + 1] = z;
        g_cnt[i] = 0;
    }
    if (i < NOUT * 12) g_S3[i] = 0.f;
    if (i < BMW) { g_bm1[i] = 0u; g_bm2[i] = 0u; }
    if (i == 0) g_nlist = 0;
}

// ---------------- S1: scan dst stream, collect edges with dst < NOUT ----------------
__global__ void k_scan1(const int* __restrict__ srcs, const int* __restrict__ dsts, int e)
{
    int t = blockIdx.x * blockDim.x + threadIdx.x;
    int base = t * 4;
    bool vecok = ((e & 3) == 0);
    if (vecok && base + 3 < e) {
        int4 d4 = *(const int4*)(dsts + base);
        int d[4] = {d4.x, d4.y, d4.z, d4.w};
        #pragma unroll
        for (int k = 0; k < 4; k++) {
            if (d[k] < NOUT) {
                int s = srcs[base + k];            // rare scalar load (~2k total)
                int idx = atomicAdd(&g_nlist, 1);
                if (idx < EE)
                    g_list[idx] = ((unsigned)d[k] << 25) | (unsigned)s;
            }
        }
    } else {
        for (int k = base; k < e && k < base + 4; k++) {
            int d = dsts[k];
            if (d < NOUT) {
                int s = srcs[k];
                int idx = atomicAdd(&g_nlist, 1);
                if (idx < EE)
                    g_list[idx] = ((unsigned)d << 25) | (unsigned)s;
            }
        }
    }
}

// ---------------- M2: bm2 = list sources + rows<NOUT; seed bm1 with the same ----------------
__global__ void k_mark2()
{
    int t = blockIdx.x * blockDim.x + threadIdx.x;
    if (t < NOUT) {
        atomicOr(&g_bm2[t >> 5], 1u << (t & 31));
        atomicOr(&g_bm1[t >> 5], 1u << (t & 31));
    }
    int nl = g_nlist;
    if (nl > EE) nl = EE;
    for (int i = t; i < nl; i += gridDim.x * blockDim.x) {
        int s = (int)(g_list[i] & 0x1FFFFFFu);
        atomicOr(&g_bm2[s >> 5], 1u << (s & 31));
        atomicOr(&g_bm1[s >> 5], 1u << (s & 31));   // bm2 rows also need cnt/S1 norm
    }
}

// ---------------- S2: scan dst stream, mark bm1[src] for edges into bm2 ----------------
__global__ void k_scan2(const int* __restrict__ srcs, const int* __restrict__ dsts, int e)
{
    int t = blockIdx.x * blockDim.x + threadIdx.x;
    int base = t * 4;
    bool vecok = ((e & 3) == 0);
    if (vecok && base + 3 < e) {
        int4 d4 = *(const int4*)(dsts + base);
        int d[4] = {d4.x, d4.y, d4.z, d4.w};
        #pragma unroll
        for (int k = 0; k < 4; k++) {
            if (bit_test(g_bm2, d[k])) {           // ~1.5% hit
                int s = srcs[base + k];
                atomicOr(&g_bm1[s >> 5], 1u << (s & 31));
            }
        }
    } else {
        for (int k = base; k < e && k < base + 4; k++) {
            int d = dsts[k];
            if (bit_test(g_bm2, d)) {
                int s = srcs[k];
                atomicOr(&g_bm1[s >> 5], 1u << (s & 31));
            }
        }
    }
}

// ---------------- S3: edge pass 1, bm1-filtered (aggregate P0 + count degrees) ----------------
__global__ void k_scan3(const int* __restrict__ srcs, const int* __restrict__ dsts, int e)
{
    int t = blockIdx.x * blockDim.x + threadIdx.x;
    int base = t * 4;
    bool vecok = ((e & 3) == 0);
    if (vecok && base + 3 < e) {
        int4 d4 = *(const int4*)(dsts + base);
        int d[4] = {d4.x, d4.y, d4.z, d4.w};
        unsigned hit = 0;
        #pragma unroll
        for (int k = 0; k < 4; k++)
            hit |= (unsigned)bit_test(g_bm1, d[k]) << k;
        if (hit == 0) return;
        int4 s4 = *(const int4*)(srcs + base);
        int s[4] = {s4.x, s4.y, s4.z, s4.w};
        #pragma unroll
        for (int k = 0; k < 4; k++) {
            if ((hit >> k) & 1u) {
                float4 a = g_P0[s[k] * 2];
                float4 b = g_P0[s[k] * 2 + 1];
                float* dp = (float*)&g_S1[d[k] * 2];
                red_v4(dp,     a.x, a.y, a.z, a.w);
                red_v4(dp + 4, b.x, b.y, b.z, b.w);
                red_s32(&g_cnt[d[k]], 1);
            }
        }
    } else {
        for (int k = base; k < e && k < base + 4; k++) {
            int d = dsts[k];
            if (!bit_test(g_bm1, d)) continue;
            int s = srcs[k];
            float4 a = g_P0[s * 2];
            float4 b = g_P0[s * 2 + 1];
            float* dp = (float*)&g_S1[d * 2];
            red_v4(dp,     a.x, a.y, a.z, a.w);
            red_v4(dp + 4, b.x, b.y, b.z, b.w);
            red_s32(&g_cnt[d], 1);
        }
    }
}

// ---------------- N: normalize S1 in place at bm1 rows ----------------
__global__ void k_norm1(int n)
{
    int i = blockIdx.x * blockDim.x + threadIdx.x;
    if (i >= n) return;
    if (!bit_test(g_bm1, i)) return;
    int c = g_cnt[i];
    float inv = 1.f / (float)(c > 1 ? c : 1);
    float4 a = g_S1[i * 2], b = g_S1[i * 2 + 1];
    a.x *= inv; a.y *= inv; a.z *= inv; a.w *= inv;
    b.x *= inv; b.y *= inv; b.z *= inv; b.w *= inv;
    g_S1[i * 2]     = a;
    g_S1[i * 2 + 1] = b;
}

// ---------------- S4: edge pass 2, bm2-filtered (aggregate A*P0) ----------------
__global__ void k_scan4(const int* __restrict__ srcs, const int* __restrict__ dsts, int e)
{
    int t = blockIdx.x * blockDim.x + threadIdx.x;
    int base = t * 4;
    bool vecok = ((e & 3) == 0);
    if (vecok && base + 3 < e) {
        int4 d4 = *(const int4*)(dsts + base);
        int d[4] = {d4.x, d4.y, d4.z, d4.w};
        unsigned hit = 0;
        #pragma unroll
        for (int k = 0; k < 4; k++)
            hit |= (unsigned)bit_test(g_bm2, d[k]) << k;
        if (hit == 0) return;
        #pragma unroll
        for (int k = 0; k < 4; k++) {
            if ((hit >> k) & 1u) {
                int s = srcs[base + k];            // rare scalar load (~1.5%)
                float4 a = g_S1[s * 2];
                float4 b = g_S1[s * 2 + 1];
                float* dp = (float*)&g_S2[d[k] * 2];
                red_v4(dp,     a.x, a.y, a.z, a.w);
                red_v4(dp + 4, b.x, b.y, b.z, b.w);
            }
        }
    } else {
        for (int k = base; k < e && k < base + 4; k++) {
            int d = dsts[k];
            if (!bit_test(g_bm2, d)) continue;
            int s = srcs[k];
            float4 a = g_S1[s * 2];
            float4 b = g_S1[s * 2 + 1];
            float* dp = (float*)&g_S2[d * 2];
            red_v4(dp,     a.x, a.y, a.z, a.w);
            red_v4(dp + 4, b.x, b.y, b.z, b.w);
        }
    }
}

// ---------------- K4: small edge pass (dst < NOUT): aggregate P2 = S2/cnt and u-sums ----------------
__global__ void k_small()
{
    int nl = g_nlist;
    if (nl > EE) nl = EE;
    for (int t = blockIdx.x * blockDim.x + threadIdx.x; t < nl;
         t += gridDim.x * blockDim.x) {
        unsigned p = g_list[t];
        int s = (int)(p & 0x1FFFFFFu);
        int d = (int)(p >> 25);
        int c = g_cnt[s];                 // s in bm2 ⊆ bm1 -> counted in scan3
        float inv = 1.f / (float)(c > 1 ? c : 1);
        float u = (c > 0) ? 1.f : 0.f;
        float4 a = g_S2[s * 2], b = g_S2[s * 2 + 1];
        float* dp = &g_S3[d * 12];
        red_v4(dp,     a.x * inv, a.y * inv, a.z * inv, a.w * inv);
        red_v4(dp + 4, b.x * inv, b.y * inv, b.z * inv, b.w * inv);
        atomicAdd(dp + 8, u);
    }
}

// ---------------- K5: combine matrices + final 68x3 output ----------------
__global__ void k_final(const float* __restrict__ Wl1, const float* __restrict__ Wr1,
                        const float* __restrict__ b1,
                        const float* __restrict__ Wl2, const float* __restrict__ Wr2,
                        const float* __restrict__ b2,
                        const float* __restrict__ Wl3, const float* __restrict__ Wr3,
                        const float* __restrict__ b3,
                        float* __restrict__ out)
{
    __shared__ float sLL[8][16], sMix[8][16], sRR[8][16];
    __shared__ float sC3[8][3], sC2[8][3], sC1[8][3], sC0[8][3];
    __shared__ float sbL2[16], sbR2[16], scv[3], scu[3], scc[3];
    int t = threadIdx.x;

    if (t < 128) {
        int i = t >> 4, j = t & 15;
        float ll = 0.f, mx = 0.f, rr = 0.f;
        #pragma unroll
        for (int k = 0; k < 16; k++) {
            float l1 = Wl1[i * 16 + k], r1 = Wr1[i * 16 + k];
            float l2 = Wl2[k * 16 + j], r2 = Wr2[k * 16 + j];
            ll += l1 * l2;
            mx += r1 * l2 + l1 * r2;
            rr += r1 * r2;
        }
        sLL[i][j] = ll; sMix[i][j] = mx; sRR[i][j] = rr;
    }
    if (t < 16) {
        float bl = 0.f, br = 0.f;
        #pragma unroll
        for (int k = 0; k < 16; k++) {
            bl += b1[k] * Wl2[k * 16 + t];
            br += b1[k] * Wr2[k * 16 + t];
        }
        sbL2[t] = bl;
        sbR2[t] = br + b2[t];
    }
    __syncthreads();

    if (t < 24) {
        int i = t / 3, cc3 = t % 3;
        float c3 = 0.f, c2 = 0.f, c1 = 0.f, c0 = 0.f;
        #pragma unroll
        for (int k = 0; k < 16; k++) {
            float l3 = Wl3[k * 3 + cc3], r3 = Wr3[k * 3 + cc3];
            c3 += sLL[i][k] * l3;
            c2 += sMix[i][k] * l3 + sLL[i][k] * r3;
            c1 += sRR[i][k] * l3 + sMix[i][k] * r3;
            c0 += sRR[i][k] * r3;
        }
        sC3[i][cc3] = c3; sC2[i][cc3] = c2; sC1[i][cc3] = c1; sC0[i][cc3] = c0;
    }
    if (t < 3) {
        float cv = 0.f, cu = 0.f, cc = 0.f;
        #pragma unroll
        for (int k = 0; k < 16; k++) {
            float l3 = Wl3[k * 3 + t], r3 = Wr3[k * 3 + t];
            cv += sbL2[k] * l3;
            cu += sbR2[k] * l3 + sbL2[k] * r3;
            cc += sbR2[k] * r3;
        }
        scv[t] = cv; scu[t] = cu; scc[t] = cc + b3[t];
    }
    __syncthreads();

    if (t < NOUT) {
        int c = g_cnt[t];                 // rows<NOUT in bm1
        float inv = 1.f / (float)(c > 1 ? c : 1);
        float u = (c > 0) ? 1.f : 0.f;
        float P0r[8], P1r[8], P2r[8], P3r[8];
        float4 a, b;
        a = g_P0[t * 2]; b = g_P0[t * 2 + 1];
        P0r[0] = a.x; P0r[1] = a.y; P0r[2] = a.z; P0r[3] = a.w;
        P0r[4] = b.x; P0r[5] = b.y; P0r[6] = b.z; P0r[7] = b.w;
        a = g_S1[t * 2]; b = g_S1[t * 2 + 1];   // normalized (rows<NOUT in bm1)
        P1r[0] = a.x; P1r[1] = a.y; P1r[2] = a.z; P1r[3] = a.w;
        P1r[4] = b.x; P1r[5] = b.y; P1r[6] = b.z; P1r[7] = b.w;
        a = g_S2[t * 2]; b = g_S2[t * 2 + 1];   // rows<NOUT in bm2
        P2r[0] = a.x * inv; P2r[1] = a.y * inv; P2r[2] = a.z * inv; P2r[3] = a.w * inv;
        P2r[4] = b.x * inv; P2r[5] = b.y * inv; P2r[6] = b.z * inv; P2r[7] = b.w * inv;
        #pragma unroll
        for (int k = 0; k < 8; k++) P3r[k] = g_S3[t * 12 + k] * inv;
        float v = g_S3[t * 12 + 8] * inv;

        #pragma unroll
        for (int cc3 = 0; cc3 < 3; cc3++) {
            float acc = scc[cc3] + u * scu[cc3] + v * scv[cc3];
            #pragma unroll
            for (int k = 0; k < 8; k++) {
                acc += P3r[k] * sC3[k][cc3]
                     + P2r[k] * sC2[k][cc3]
                     + P1r[k] * sC1[k][cc3]
                     + P0r[k] * sC0[k][cc3];
            }
            out[t * 3 + cc3] = acc;
        }
    }
}

// ---------------- launch ----------------
extern "C" void kernel_launch(void* const* d_in, const int* in_sizes, int n_in,
                              void* d_out, int out_size)
{
    const float* x    = (const float*)d_in[0];
    const int*   ei   = (const int*)  d_in[1];
    const float* wpos = (const float*)d_in[2];
    const float* bpos = (const float*)d_in[3];
    const float* Wl1  = (const float*)d_in[4];
    const float* Wr1  = (const float*)d_in[5];
    const float* b1   = (const float*)d_in[6];
    const float* Wl2  = (const float*)d_in[7];
    const float* Wr2  = (const float*)d_in[8];
    const float* b2   = (const float*)d_in[9];
    const float* Wl3  = (const float*)d_in[10];
    const float* Wr3  = (const float*)d_in[11];
    const float* b3   = (const float*)d_in[12];

    int n = in_sizes[0] / 3;
    int e = in_sizes[1] / 2;
    if (n > NPAD) n = NPAD;   // scratch capacity guard (problem-fixed N=150000)
    if (e > EE)   e = EE;

    int nb = (n + 255) / 256;
    if (nb < 4) nb = 4;       // ensure S3/bitmap/counter zeroing coverage
    int eb = ((e + 3) / 4 + 255) / 256;

    k_init  <<<nb, 256>>>(x, wpos, bpos, n);
    k_scan1 <<<eb, 256>>>(ei, ei + e, e);
    k_mark2 <<<16, 256>>>();
    k_scan2 <<<eb, 256>>>(ei, ei + e, e);
    k_scan3 <<<eb, 256>>>(ei, ei + e, e);
    k_norm1 <<<nb, 256>>>(n);
    k_scan4 <<<eb, 256>>>(ei, ei + e, e);
    k_small <<<64, 256>>>();
    k_final <<<1, 128>>>(Wl1, Wr1, b1, Wl2, Wr2, b2, Wl3, Wr3, b3, (float*)d_out);
}